// round 2
// baseline (speedup 1.0000x reference)
#include <cuda_runtime.h>
#include <math.h>

#define B_    32
#define T_    512
#define IN_   256
#define PRE_  512
#define LH_   512
#define NHID  1024
#define ACTH  512
#define NPOL  64
#define MTOT  (B_ * T_)      // 16384
#define G4    (4 * NHID)     // 4096

// ---------------- scratch (device globals; no allocation allowed) ----------------
__device__ float g_h [(size_t)MTOT * PRE_];
__device__ float g_u [(size_t)MTOT * LH_];
__device__ float g_xg[(size_t)MTOT * G4];
__device__ float g_hs[(size_t)MTOT * NHID];
__device__ float g_a [(size_t)MTOT * ACTH];
__device__ float g_v [(size_t)MTOT * ACTH];
__device__ float g_hstA[B_ * NHID];
__device__ float g_hstB[B_ * NHID];
__device__ float g_cst [B_ * NHID];

// ---------------- zero init for recurrent state ----------------
__global__ void zero_states(float* a, float* c, int n) {
    int i = blockIdx.x * blockDim.x + threadIdx.x;
    if (i < n) { a[i] = 0.0f; c[i] = 0.0f; }
}

// ---------------- generic tiled SGEMM: C[m,n] = act(sum_k A[m,k]*W[n,k] + b1[n] (+ b2[n])) ----
// A: [M,K] row-major, W: [N,K] row-major. BM=BN=64, BK=16, 256 threads, 4x4 micro-tile.
#define BM 64
#define BN 64
#define BK 16

template<bool RELU>
__global__ void sgemm_bias(const float* __restrict__ A, const float* __restrict__ W,
                           const float* __restrict__ bias1, const float* __restrict__ bias2,
                           float* __restrict__ C, int M, int N, int K) {
    __shared__ float As[BK][BM + 4];
    __shared__ float Ws[BK][BN + 4];

    const int tid = threadIdx.x;
    const int tx = tid & 15;          // n micro index
    const int ty = tid >> 4;          // m micro index
    const int m0 = blockIdx.y * BM;
    const int n0 = blockIdx.x * BN;

    const int lrow = tid >> 2;        // 0..63
    const int lkq  = (tid & 3) * 4;   // 0,4,8,12

    float acc[4][4] = {};

    for (int k0 = 0; k0 < K; k0 += BK) {
        float4 av = *(const float4*)&A[(size_t)(m0 + lrow) * K + k0 + lkq];
        float4 wv = *(const float4*)&W[(size_t)(n0 + lrow) * K + k0 + lkq];
        As[lkq + 0][lrow] = av.x; As[lkq + 1][lrow] = av.y;
        As[lkq + 2][lrow] = av.z; As[lkq + 3][lrow] = av.w;
        Ws[lkq + 0][lrow] = wv.x; Ws[lkq + 1][lrow] = wv.y;
        Ws[lkq + 2][lrow] = wv.z; Ws[lkq + 3][lrow] = wv.w;
        __syncthreads();

        #pragma unroll
        for (int kk = 0; kk < BK; kk++) {
            float4 a4 = *(const float4*)&As[kk][ty * 4];
            float4 w4 = *(const float4*)&Ws[kk][tx * 4];
            float am[4] = {a4.x, a4.y, a4.z, a4.w};
            float wn[4] = {w4.x, w4.y, w4.z, w4.w};
            #pragma unroll
            for (int i = 0; i < 4; i++)
                #pragma unroll
                for (int j = 0; j < 4; j++)
                    acc[i][j] = fmaf(am[i], wn[j], acc[i][j]);
        }
        __syncthreads();
    }

    float4 bv = *(const float4*)&bias1[n0 + tx * 4];
    if (bias2) {
        float4 b2 = *(const float4*)&bias2[n0 + tx * 4];
        bv.x += b2.x; bv.y += b2.y; bv.z += b2.z; bv.w += b2.w;
    }
    float bn[4] = {bv.x, bv.y, bv.z, bv.w};

    #pragma unroll
    for (int i = 0; i < 4; i++) {
        float4 o;
        float* op = &o.x;
        #pragma unroll
        for (int j = 0; j < 4; j++) {
            float val = acc[i][j] + bn[j];
            if (RELU) val = fmaxf(val, 0.0f);
            op[j] = val;
        }
        *(float4*)&C[(size_t)(m0 + ty * 4 + i) * N + n0 + tx * 4] = o;
    }
}

// ---------------- LSTM step: gates = xg[:,t,:] + h @ Whh^T, cell update ----------------
// grid = 128 blocks (8 hidden units each), 256 threads.
// warp w owns j = blockIdx.x*8 + w, all 4 gates; lane = batch index.
#define KC 128

__global__ void lstm_step(const float* __restrict__ Whh,
                          const float* __restrict__ xg,
                          const float* __restrict__ hin,
                          float* __restrict__ hout,
                          float* __restrict__ cst,
                          float* __restrict__ hs,
                          int t) {
    __shared__ float ht[KC][33];   // [kk][b], pad for conflict-free compute reads

    const int tid  = threadIdx.x;
    const int lane = tid & 31;     // batch
    const int w    = tid >> 5;     // warp -> hidden unit within block
    const int j    = blockIdx.x * 8 + w;

    const float* w0 = Whh + (size_t)(0 * NHID + j) * NHID;
    const float* w1 = Whh + (size_t)(1 * NHID + j) * NHID;
    const float* w2 = Whh + (size_t)(2 * NHID + j) * NHID;
    const float* w3 = Whh + (size_t)(3 * NHID + j) * NHID;

    float a0 = 0.f, a1 = 0.f, a2 = 0.f, a3 = 0.f;

    for (int kc = 0; kc < NHID; kc += KC) {
        // stage h chunk [32 x 128] into shared, transposed to [kk][b]
        #pragma unroll
        for (int it = 0; it < 4; it++) {
            int idx = tid + it * 256;      // 0..1023 float4 slots
            int b   = idx >> 5;            // 0..31
            int kq  = (idx & 31) * 4;      // 0..124
            float4 v = *(const float4*)&hin[b * NHID + kc + kq];
            ht[kq + 0][b] = v.x; ht[kq + 1][b] = v.y;
            ht[kq + 2][b] = v.z; ht[kq + 3][b] = v.w;
        }
        __syncthreads();

        #pragma unroll 2
        for (int kk = 0; kk < KC; kk += 4) {
            float4 v0 = *(const float4*)&w0[kc + kk];
            float4 v1 = *(const float4*)&w1[kc + kk];
            float4 v2 = *(const float4*)&w2[kc + kk];
            float4 v3 = *(const float4*)&w3[kc + kk];
            float h0 = ht[kk + 0][lane];
            float h1 = ht[kk + 1][lane];
            float h2 = ht[kk + 2][lane];
            float h3 = ht[kk + 3][lane];
            a0 = fmaf(v0.x, h0, a0); a0 = fmaf(v0.y, h1, a0);
            a0 = fmaf(v0.z, h2, a0); a0 = fmaf(v0.w, h3, a0);
            a1 = fmaf(v1.x, h0, a1); a1 = fmaf(v1.y, h1, a1);
            a1 = fmaf(v1.z, h2, a1); a1 = fmaf(v1.w, h3, a1);
            a2 = fmaf(v2.x, h0, a2); a2 = fmaf(v2.y, h1, a2);
            a2 = fmaf(v2.z, h2, a2); a2 = fmaf(v2.w, h3, a2);
            a3 = fmaf(v3.x, h0, a3); a3 = fmaf(v3.y, h1, a3);
            a3 = fmaf(v3.z, h2, a3); a3 = fmaf(v3.w, h3, a3);
        }
        __syncthreads();
    }

    // cell update: thread (lane=b, warp=j) owns all four gates
    const int b = lane;
    const float* xr = xg + ((size_t)b * T_ + t) * G4;
    float gi = a0 + xr[0 * NHID + j];
    float gf = a1 + xr[1 * NHID + j];
    float gg = a2 + xr[2 * NHID + j];
    float go = a3 + xr[3 * NHID + j];

    float si = 1.0f / (1.0f + expf(-gi));
    float sf = 1.0f / (1.0f + expf(-gf));
    float so = 1.0f / (1.0f + expf(-go));

    float c = sf * cst[b * NHID + j] + si * tanhf(gg);
    float h = so * tanhf(c);

    cst[b * NHID + j] = c;
    hout[b * NHID + j] = h;
    hs[((size_t)b * T_ + t) * NHID + j] = h;
}

// ---------------- softmax over last dim (64) in place ----------------
__global__ void softmax64(float* __restrict__ logits) {
    const int row  = blockIdx.x * 4 + (threadIdx.x >> 5);
    const int lane = threadIdx.x & 31;
    float* p = logits + (size_t)row * NPOL;
    float v0 = p[lane], v1 = p[lane + 32];
    float m = fmaxf(v0, v1);
    #pragma unroll
    for (int off = 16; off > 0; off >>= 1)
        m = fmaxf(m, __shfl_xor_sync(0xffffffffu, m, off));
    float e0 = expf(v0 - m), e1 = expf(v1 - m);
    float s = e0 + e1;
    #pragma unroll
    for (int off = 16; off > 0; off >>= 1)
        s += __shfl_xor_sync(0xffffffffu, s, off);
    float inv = 1.0f / s;
    p[lane] = e0 * inv;
    p[lane + 32] = e1 * inv;
}

// ---------------- value head: out[m] = dot(V[m,:512], w) + b[0] ----------------
__global__ void matvec_val(const float* __restrict__ V, const float* __restrict__ w,
                           const float* __restrict__ bias, float* __restrict__ out) {
    const int row  = blockIdx.x * 8 + (threadIdx.x >> 5);
    const int lane = threadIdx.x & 31;
    const float* vr = V + (size_t)row * ACTH;
    float s = 0.0f;
    #pragma unroll
    for (int q = 0; q < 4; q++) {
        int k = q * 128 + lane * 4;
        float4 a = *(const float4*)&vr[k];
        float4 b = *(const float4*)&w[k];
        s = fmaf(a.x, b.x, s); s = fmaf(a.y, b.y, s);
        s = fmaf(a.z, b.z, s); s = fmaf(a.w, b.w, s);
    }
    #pragma unroll
    for (int off = 16; off > 0; off >>= 1)
        s += __shfl_xor_sync(0xffffffffu, s, off);
    if (lane == 0) out[row] = s + bias[0];
}

// ---------------- launch ----------------
extern "C" void kernel_launch(void* const* d_in, const int* in_sizes, int n_in,
                              void* d_out, int out_size) {
    const float* x        = (const float*)d_in[0];
    const float* pre_W0   = (const float*)d_in[1];
    const float* pre_b0   = (const float*)d_in[2];
    const float* pre_W1   = (const float*)d_in[3];
    const float* pre_b1   = (const float*)d_in[4];
    const float* w_ih     = (const float*)d_in[5];
    const float* w_hh     = (const float*)d_in[6];
    const float* b_ih     = (const float*)d_in[7];
    const float* b_hh     = (const float*)d_in[8];
    const float* act_W0   = (const float*)d_in[9];
    const float* act_b0   = (const float*)d_in[10];
    const float* act_W1   = (const float*)d_in[11];
    const float* act_b1   = (const float*)d_in[12];
    const float* val_W0   = (const float*)d_in[13];
    const float* val_b0   = (const float*)d_in[14];
    const float* val_W1   = (const float*)d_in[15];
    const float* val_b1   = (const float*)d_in[16];

    float* out_probs = (float*)d_out;
    float* out_value = (float*)d_out + (size_t)MTOT * NPOL;

    float *pH, *pU, *pXG, *pHS, *pA, *pV, *pHA, *pHB, *pC;
    cudaGetSymbolAddress((void**)&pH,  g_h);
    cudaGetSymbolAddress((void**)&pU,  g_u);
    cudaGetSymbolAddress((void**)&pXG, g_xg);
    cudaGetSymbolAddress((void**)&pHS, g_hs);
    cudaGetSymbolAddress((void**)&pA,  g_a);
    cudaGetSymbolAddress((void**)&pV,  g_v);
    cudaGetSymbolAddress((void**)&pHA, g_hstA);
    cudaGetSymbolAddress((void**)&pHB, g_hstB);
    cudaGetSymbolAddress((void**)&pC,  g_cst);

    // zero recurrent state
    zero_states<<<(B_ * NHID + 255) / 256, 256>>>(pHA, pC, B_ * NHID);

    // pre_dnn
    sgemm_bias<true ><<<dim3(PRE_ / BN, MTOT / BM), 256>>>(x,  pre_W0, pre_b0, nullptr, pH, MTOT, PRE_, IN_);
    sgemm_bias<false><<<dim3(LH_  / BN, MTOT / BM), 256>>>(pH, pre_W1, pre_b1, nullptr, pU, MTOT, LH_, PRE_);

    // input contribution to gates (+ both biases)
    sgemm_bias<false><<<dim3(G4 / BN, MTOT / BM), 256>>>(pU, w_ih, b_ih, b_hh, pXG, MTOT, G4, LH_);

    // sequential recurrence, double-buffered h state
    for (int t = 0; t < T_; t++) {
        const float* hin = (t & 1) ? pHB : pHA;
        float*       hot = (t & 1) ? pHA : pHB;
        lstm_step<<<NHID / 8, 256>>>(w_hh, pXG, hin, hot, pC, pHS, t);
    }

    // policy head
    sgemm_bias<true ><<<dim3(ACTH / BN, MTOT / BM), 256>>>(pHS, act_W0, act_b0, nullptr, pA, MTOT, ACTH, NHID);
    sgemm_bias<false><<<dim3(NPOL / BN, MTOT / BM), 256>>>(pA, act_W1, act_b1, nullptr, out_probs, MTOT, NPOL, ACTH);
    softmax64<<<MTOT / 4, 128>>>(out_probs);

    // value head
    sgemm_bias<true ><<<dim3(ACTH / BN, MTOT / BM), 256>>>(pHS, val_W0, val_b0, nullptr, pV, MTOT, ACTH, NHID);
    matvec_val<<<MTOT / 8, 256>>>(pV, val_W1, val_b1, out_value);
}